// round 9
// baseline (speedup 1.0000x reference)
#include <cuda_runtime.h>
#include <cuda_bf16.h>
#include <cuda_fp16.h>
#include <cstdint>
#include <mma.h>

#define NN 100000
#define EE 1600000
#define HH 4
#define CC 32
#define DD 128
#define GG 64
#define NEG 0.2f
#define NB1 ((NN + 1023) / 1024)
#define NPW 8   // nodes per warp in k_gat (pipelined)

using namespace nvcuda;

// ---------------- device scratch ----------------
__device__ float g_hA[(size_t)NN * DD];
__device__ float g_hB[(size_t)NN * DD];
__device__ __half g_hlinh[(size_t)NN * DD];      // fp16 hlin (gather operand)
__device__ __nv_bfloat16 g_Ahi[(size_t)NN * DD];
__device__ __nv_bfloat16 g_Alo[(size_t)NN * DD];
__device__ __nv_bfloat16 g_Whi[3 * DD * DD];
__device__ __nv_bfloat16 g_Wlo[3 * DD * DD];
__device__ float g_asrc[NN * HH];
__device__ float g_adst[NN * HH];
__device__ int   g_deg[NN];
__device__ int   g_rowptr[NN + 1];
__device__ int   g_cursor[NN];
__device__ int   g_col[EE];
__device__ int   g_bsums[128];

__device__ __forceinline__ float lrelu(float x) { return x > 0.f ? x : NEG * x; }

// ---------------- init (zero + W bf16-split fused) ----------------
__global__ void k_zero(float* __restrict__ gout, const float* __restrict__ Ws) {
    int i = blockIdx.x * blockDim.x + threadIdx.x;
    if (i < NN) g_deg[i] = 0;
    if (i < GG * DD) gout[i] = 0.f;
    if (i < 3 * DD * DD) {
        float f = Ws[i];
        __nv_bfloat16 hi = __float2bfloat16(f);
        g_Whi[i] = hi;
        g_Wlo[i] = __float2bfloat16(f - __bfloat162float(hi));
    }
}

__global__ void k_count(const int* __restrict__ ei) {
    int e = blockIdx.x * blockDim.x + threadIdx.x;
    if (e < EE) atomicAdd(&g_deg[ei[EE + e]], 1);
}

__global__ void k_scan_block() {
    __shared__ int s[1024];
    int i = blockIdx.x * 1024 + threadIdx.x;
    int v = (i < NN) ? g_deg[i] : 0;
    s[threadIdx.x] = v;
    __syncthreads();
    for (int off = 1; off < 1024; off <<= 1) {
        int t = (threadIdx.x >= off) ? s[threadIdx.x - off] : 0;
        __syncthreads();
        s[threadIdx.x] += t;
        __syncthreads();
    }
    if (i < NN) g_rowptr[i] = s[threadIdx.x] - v;
    if (threadIdx.x == 1023) g_bsums[blockIdx.x] = s[1023];
}

__global__ void k_scan_bsums() {
    __shared__ int s[128];
    int t = threadIdx.x;
    int v = (t < NB1) ? g_bsums[t] : 0;
    s[t] = v;
    __syncthreads();
    for (int off = 1; off < 128; off <<= 1) {
        int u = (t >= off) ? s[t - off] : 0;
        __syncthreads();
        s[t] += u;
        __syncthreads();
    }
    if (t < NB1) g_bsums[t] = s[t] - v;
}

__global__ void k_scan_add() {
    int i = blockIdx.x * blockDim.x + threadIdx.x;
    if (i < NN) {
        int v = g_rowptr[i] + g_bsums[i >> 10];
        g_rowptr[i] = v;
        g_cursor[i] = v;
    }
    if (i == 0) g_rowptr[NN] = EE;
}

__global__ void k_fill(const int* __restrict__ ei) {
    int e = blockIdx.x * blockDim.x + threadIdx.x;
    if (e < EE) {
        int src = ei[e];
        int dst = ei[EE + e];
        int pos = atomicAdd(&g_cursor[dst], 1);
        g_col[pos] = src;
    }
}

// ---------------- layer-0 GEMM [NN,7]@[7,128] + fused alpha ----------------
__global__ __launch_bounds__(128) void k_gemm0(const float* __restrict__ x,
                                               const float* __restrict__ W,
                                               const float* __restrict__ aws,
                                               const float* __restrict__ awd,
                                               __half* __restrict__ outh) {
    __shared__ float Ws[7 * 128];
    __shared__ float xs[8 * 7];
    int t = threadIdx.x;
    int w = t >> 5, lane = t & 31;
    for (int i = t; i < 7 * 128; i += 128) Ws[i] = W[i];
    int base = blockIdx.x * 8;
    for (int i = t; i < 8 * 7; i += 128) {
        int nn = base + i / 7;
        xs[i] = (nn < NN) ? x[nn * 7 + (i % 7)] : 0.f;
    }
    float awsv = aws[t], awdv = awd[t];
    __syncthreads();
    for (int j = 0; j < 8; j++) {
        int n = base + j;
        if (n < NN) {
            float s = 0.f;
#pragma unroll
            for (int k = 0; k < 7; k++) s = fmaf(xs[j * 7 + k], Ws[k * 128 + t], s);
            outh[(size_t)n * DD + t] = __float2half(s);
            float ps = s * awsv, pd = s * awdv;
#pragma unroll
            for (int o = 16; o >= 1; o >>= 1) {
                ps += __shfl_xor_sync(0xffffffffu, ps, o);
                pd += __shfl_xor_sync(0xffffffffu, pd, o);
            }
            if (lane == 0) {
                g_asrc[n * 4 + w] = ps;
                g_adst[n * 4 + w] = pd;
            }
        }
    }
}

// ---------------- layers 1-3 GEMM: wmma bf16 split + fused alpha, fp16 output
#define BSTRIDE 136
#define ASTRIDE 40
#define SMEM_TC2 91136

__global__ __launch_bounds__(256, 2)
void k_gemm_tc(const __nv_bfloat16* __restrict__ Ahi, const __nv_bfloat16* __restrict__ Alo,
               const __nv_bfloat16* __restrict__ Whi, const __nv_bfloat16* __restrict__ Wlo,
               __half* __restrict__ Couth,
               const float* __restrict__ aw_src, const float* __restrict__ aw_dst) {
    extern __shared__ char dsm[];
    float* awsS = (float*)dsm;
    float* awdS = (float*)(dsm + 512);
    __nv_bfloat16* Bh = (__nv_bfloat16*)(dsm + 1024);
    __nv_bfloat16* Bl = (__nv_bfloat16*)(dsm + 35840);
    __nv_bfloat16* Ah = (__nv_bfloat16*)(dsm + 70656);
    __nv_bfloat16* Al = (__nv_bfloat16*)(dsm + 80896);
    const int tid = threadIdx.x;
    const int wid = tid >> 5;
    const int lane = tid & 31;
    const int row0 = blockIdx.x * 128;
    const int warp_m = wid & 3;
    const int warp_n = wid >> 2;

    if (tid < 128) {
        awsS[tid] = aw_src[tid];
        awdS[tid] = aw_dst[tid];
    }
    {
        int br = tid >> 1, cb = (tid & 1) * 64;
        const uint4* sh = (const uint4*)&Whi[br * DD + cb];
        const uint4* sl = (const uint4*)&Wlo[br * DD + cb];
        uint4* dh = (uint4*)&Bh[br * BSTRIDE + cb];
        uint4* dl = (uint4*)&Bl[br * BSTRIDE + cb];
#pragma unroll
        for (int i = 0; i < 8; i++) { dh[i] = sh[i]; dl[i] = sl[i]; }
    }
    const int ar = tid >> 1;
    const int akb = (tid & 1) * 16;
    const size_t agrow = (size_t)min(row0 + ar, NN - 1) * DD;
#define LOAD_A(c)                                                             \
    do {                                                                      \
        const uint4* sh_ = (const uint4*)&Ahi[agrow + (c) * 32 + akb];        \
        const uint4* sl_ = (const uint4*)&Alo[agrow + (c) * 32 + akb];        \
        uint4* dh_ = (uint4*)&Ah[ar * ASTRIDE + akb];                         \
        uint4* dl_ = (uint4*)&Al[ar * ASTRIDE + akb];                         \
        dh_[0] = sh_[0]; dh_[1] = sh_[1];                                     \
        dl_[0] = sl_[0]; dl_[1] = sl_[1];                                     \
    } while (0)

    wmma::fragment<wmma::accumulator, 16, 16, 16, float> acc[2][4];
#pragma unroll
    for (int im = 0; im < 2; im++)
#pragma unroll
        for (int in = 0; in < 4; in++) wmma::fill_fragment(acc[im][in], 0.f);

    LOAD_A(0);
    __syncthreads();

#pragma unroll
    for (int c = 0; c < 4; c++) {
#pragma unroll
        for (int ksl = 0; ksl < 2; ksl++) {
            wmma::fragment<wmma::matrix_a, 16, 16, 16, __nv_bfloat16, wmma::row_major> ah[2], al[2];
#pragma unroll
            for (int im = 0; im < 2; im++) {
                wmma::load_matrix_sync(ah[im], &Ah[(warp_m * 32 + im * 16) * ASTRIDE + ksl * 16], ASTRIDE);
                wmma::load_matrix_sync(al[im], &Al[(warp_m * 32 + im * 16) * ASTRIDE + ksl * 16], ASTRIDE);
            }
            const int krow = c * 32 + ksl * 16;
#pragma unroll
            for (int in = 0; in < 4; in++) {
                wmma::fragment<wmma::matrix_b, 16, 16, 16, __nv_bfloat16, wmma::row_major> bh, bl;
                wmma::load_matrix_sync(bh, &Bh[krow * BSTRIDE + warp_n * 64 + in * 16], BSTRIDE);
                wmma::load_matrix_sync(bl, &Bl[krow * BSTRIDE + warp_n * 64 + in * 16], BSTRIDE);
#pragma unroll
                for (int im = 0; im < 2; im++) {
                    wmma::mma_sync(acc[im][in], ah[im], bh, acc[im][in]);
                    wmma::mma_sync(acc[im][in], al[im], bh, acc[im][in]);
                    wmma::mma_sync(acc[im][in], ah[im], bl, acc[im][in]);
                }
            }
        }
        __syncthreads();
        if (c < 3) {
            LOAD_A(c + 1);
            __syncthreads();
        }
    }

    float* osm = (float*)(dsm + 1024);
#pragma unroll
    for (int im = 0; im < 2; im++)
#pragma unroll
        for (int in = 0; in < 4; in++)
            wmma::store_matrix_sync(&osm[(warp_m * 32 + im * 16) * BSTRIDE + warp_n * 64 + in * 16],
                                    acc[im][in], BSTRIDE, wmma::mem_row_major);
    __syncthreads();

    if (wid < 4) {
        int r = wid * 32 + lane;
        int grow = row0 + r;
        if (grow < NN) {
#pragma unroll
            for (int b = 0; b < 4; b++) {
                float asum = 0.f, dsum = 0.f;
#pragma unroll
                for (int i = 0; i < 32; i++) {
                    float v = osm[r * BSTRIDE + b * 32 + i];
                    asum = fmaf(v, awsS[b * 32 + i], asum);
                    dsum = fmaf(v, awdS[b * 32 + i], dsum);
                }
                g_asrc[grow * 4 + b] = asum;
                g_adst[grow * 4 + b] = dsum;
            }
        }
    }
    for (int idx = tid; idx < 128 * 32; idx += 256) {
        int r = idx >> 5;
        int c4 = (idx & 31) << 2;
        if (row0 + r < NN) {
            float4 v = *(const float4*)&osm[r * BSTRIDE + c4];
            __half2 h0 = __floats2half2_rn(v.x, v.y);
            __half2 h1 = __floats2half2_rn(v.z, v.w);
            uint2 o;
            o.x = *(uint32_t*)&h0;
            o.y = *(uint32_t*)&h1;
            *(uint2*)&Couth[(size_t)(row0 + r) * DD + c4] = o;
        }
    }
#undef LOAD_A
}

// ---------------- fused single-pass GAT layer, node-pipelined ----------------
// Each warp processes NPW consecutive nodes; prefetches next node's rowptr,
// adst/asrc and first col chunk while processing the current node.
__global__ __launch_bounds__(256) void k_gat(const __half* __restrict__ hlin,
                                             const float* __restrict__ hprev,
                                             const float* __restrict__ bias,
                                             const float* __restrict__ gam,
                                             const float* __restrict__ bet,
                                             float* __restrict__ outp, int residual,
                                             int wbf) {
    __shared__ float es[8][32][8];
    const int lane = threadIdx.x & 31;
    const int wslot = threadIdx.x >> 5;
    const int gw = blockIdx.x * 8 + wslot;
    const int start = gw * NPW;
    if (start >= NN) return;
    const int end = min(start + NPW, NN);
    const int hd = lane >> 3;

    // prefetch for first node
    int rs_n = __ldg(&g_rowptr[start]);
    int re_n = __ldg(&g_rowptr[start + 1]);
    float4 ad_n = *(const float4*)&g_adst[(size_t)start * 4];
    float4 as_n = *(const float4*)&g_asrc[(size_t)start * 4];
    int s_pf = __ldg(&g_col[min(rs_n + lane, EE - 1)]);

    const float2* ep = (const float2*)&es[wslot][0][hd * 2];

    for (int n = start; n < end; n++) {
        const int rs = rs_n, re = re_n;
        const float4 ad4 = ad_n, as4 = as_n;
        const int s_first = s_pf;
        if (n + 1 < end) {
            rs_n = re;                               // rowptr[n+1] already known
            re_n = __ldg(&g_rowptr[n + 2]);
            ad_n = *(const float4*)&g_adst[(size_t)(n + 1) * 4];
            as_n = *(const float4*)&g_asrc[(size_t)(n + 1) * 4];
            s_pf = __ldg(&g_col[min(re + lane, EE - 1)]);
        }

        const float ad0 = ad4.x, ad1 = ad4.y, ad2 = ad4.z, ad3 = ad4.w;
        float w0 = __expf(lrelu(as4.x + ad0));
        float w1 = __expf(lrelu(as4.y + ad1));
        float w2 = __expf(lrelu(as4.z + ad2));
        float w3 = __expf(lrelu(as4.w + ad3));
        float z0 = (lane == 0) ? w0 : 0.f;
        float z1 = (lane == 0) ? w1 : 0.f;
        float z2 = (lane == 0) ? w2 : 0.f;
        float z3 = (lane == 0) ? w3 : 0.f;

        float wslf = (hd == 0) ? w0 : (hd == 1) ? w1 : (hd == 2) ? w2 : w3;
        uint2 sp = *(const uint2*)&hlin[(size_t)n * DD + lane * 4];
        float2 sf01 = __half22float2(*(__half2*)&sp.x);
        float2 sf23 = __half22float2(*(__half2*)&sp.y);
        float a0 = sf01.x * wslf, a1 = sf01.y * wslf, a2 = sf23.x * wslf, a3 = sf23.y * wslf;

        for (int c = rs; c < re; c += 32) {
            int cnt = re - c;
            if (cnt > 32) cnt = 32;
            int s = (c == rs) ? s_first : __ldg(&g_col[min(c + lane, EE - 1)]);
            if (lane < cnt) {
                float4 a = *(const float4*)&g_asrc[(size_t)s * 4];
                float e0 = __expf(lrelu(a.x + ad0));
                float e1 = __expf(lrelu(a.y + ad1));
                float e2 = __expf(lrelu(a.z + ad2));
                float e3 = __expf(lrelu(a.w + ad3));
                z0 += e0; z1 += e1; z2 += e2; z3 += e3;
                float sv = __int_as_float(s);
                *(float4*)&es[wslot][lane][0] = make_float4(e0, sv, e1, sv);
                *(float4*)&es[wslot][lane][4] = make_float4(e2, sv, e3, sv);
            }
            __syncwarp();
#pragma unroll 4
            for (int j = 0; j < cnt; j++) {
                float2 wsj = ep[j * 4];            // (e_hd, src) in one LDS.64
                float wj = wsj.x;
                int sj = __float_as_int(wsj.y);
                uint2 p = *(const uint2*)&hlin[(size_t)sj * DD + lane * 4];
                float2 f01 = __half22float2(*(__half2*)&p.x);
                float2 f23 = __half22float2(*(__half2*)&p.y);
                a0 = fmaf(f01.x, wj, a0);
                a1 = fmaf(f01.y, wj, a1);
                a2 = fmaf(f23.x, wj, a2);
                a3 = fmaf(f23.y, wj, a3);
            }
            __syncwarp();
        }
#pragma unroll
        for (int o = 16; o >= 1; o >>= 1) {
            z0 += __shfl_xor_sync(0xffffffffu, z0, o);
            z1 += __shfl_xor_sync(0xffffffffu, z1, o);
            z2 += __shfl_xor_sync(0xffffffffu, z2, o);
            z3 += __shfl_xor_sync(0xffffffffu, z3, o);
        }
        float zh = (hd == 0) ? z0 : (hd == 1) ? z1 : (hd == 2) ? z2 : z3;
        float invz = 1.f / (zh + 1e-16f);
        a0 *= invz; a1 *= invz; a2 *= invz; a3 *= invz;

        float4 bv = *(const float4*)&bias[lane * 4];
        a0 += bv.x; a1 += bv.y; a2 += bv.z; a3 += bv.w;
        float sm = a0 + a1 + a2 + a3;
#pragma unroll
        for (int o = 16; o >= 1; o >>= 1) sm += __shfl_xor_sync(0xffffffffu, sm, o);
        float mean = sm * (1.f / DD);
        float d0 = a0 - mean, d1 = a1 - mean, d2 = a2 - mean, d3 = a3 - mean;
        float sq = d0 * d0 + d1 * d1 + d2 * d2 + d3 * d3;
#pragma unroll
        for (int o = 16; o >= 1; o >>= 1) sq += __shfl_xor_sync(0xffffffffu, sq, o);
        float rstd = rsqrtf(sq * (1.f / DD) + 1e-5f);
        float4 gv = *(const float4*)&gam[lane * 4];
        float4 bev = *(const float4*)&bet[lane * 4];
        float v0 = d0 * rstd * gv.x + bev.x;
        float v1 = d1 * rstd * gv.y + bev.y;
        float v2 = d2 * rstd * gv.z + bev.z;
        float v3 = d3 * rstd * gv.w + bev.w;
        v0 = v0 > 0.f ? v0 : __expf(v0) - 1.f;
        v1 = v1 > 0.f ? v1 : __expf(v1) - 1.f;
        v2 = v2 > 0.f ? v2 : __expf(v2) - 1.f;
        v3 = v3 > 0.f ? v3 : __expf(v3) - 1.f;
        if (residual) {
            float4 pv = *(const float4*)&hprev[(size_t)n * DD + lane * 4];
            v0 += pv.x; v1 += pv.y; v2 += pv.z; v3 += pv.w;
        }
        *(float4*)&outp[(size_t)n * DD + lane * 4] = make_float4(v0, v1, v2, v3);

        if (wbf) {
            __nv_bfloat16 h0 = __float2bfloat16(v0);
            __nv_bfloat16 h1 = __float2bfloat16(v1);
            __nv_bfloat16 h2 = __float2bfloat16(v2);
            __nv_bfloat16 h3 = __float2bfloat16(v3);
            __nv_bfloat16 l0 = __float2bfloat16(v0 - __bfloat162float(h0));
            __nv_bfloat16 l1 = __float2bfloat16(v1 - __bfloat162float(h1));
            __nv_bfloat16 l2 = __float2bfloat16(v2 - __bfloat162float(h2));
            __nv_bfloat16 l3 = __float2bfloat16(v3 - __bfloat162float(h3));
            uint2 ph, pl;
            ph.x = (uint32_t)__bfloat16_as_ushort(h0) | ((uint32_t)__bfloat16_as_ushort(h1) << 16);
            ph.y = (uint32_t)__bfloat16_as_ushort(h2) | ((uint32_t)__bfloat16_as_ushort(h3) << 16);
            pl.x = (uint32_t)__bfloat16_as_ushort(l0) | ((uint32_t)__bfloat16_as_ushort(l1) << 16);
            pl.y = (uint32_t)__bfloat16_as_ushort(l2) | ((uint32_t)__bfloat16_as_ushort(l3) << 16);
            *(uint2*)&g_Ahi[(size_t)n * DD + lane * 4] = ph;
            *(uint2*)&g_Alo[(size_t)n * DD + lane * 4] = pl;
        }
    }
}

// ---------------- graph pooling ----------------
__global__ __launch_bounds__(128) void k_pool(const float* __restrict__ ne,
                                              const int* __restrict__ batch,
                                              float* __restrict__ gout) {
    int base = blockIdx.x * 128;
    if (base >= NN) return;
    int d = threadIdx.x;
    int end = base + 128;
    if (end > NN) end = NN;
    float acc = 0.f;
    int cg = __ldg(&batch[base]);
    for (int n = base; n < end; n++) {
        int gidx = __ldg(&batch[n]);
        if (gidx != cg) {
            atomicAdd(&gout[cg * DD + d], acc);
            acc = 0.f;
            cg = gidx;
        }
        acc += ne[(size_t)n * DD + d];
    }
    atomicAdd(&gout[cg * DD + d], acc);
}

// per-graph counts via binary search on sorted batch
__global__ void k_final(float* __restrict__ gout, const int* __restrict__ batch) {
    int g = blockIdx.x;
    int d = threadIdx.x;
    __shared__ int cnt_s;
    if (d == 0) {
        int lo = 0, hi = NN;
        while (lo < hi) { int m = (lo + hi) >> 1; if (batch[m] < g) lo = m + 1; else hi = m; }
        int lb = lo;
        lo = lb; hi = NN;
        while (lo < hi) { int m = (lo + hi) >> 1; if (batch[m] < g + 1) lo = m + 1; else hi = m; }
        cnt_s = lo - lb;
    }
    __syncthreads();
    gout[g * DD + d] /= fmaxf((float)cnt_s, 1.f);
}

// ---------------- host launch ----------------
extern "C" void kernel_launch(void* const* d_in, const int* in_sizes, int n_in,
                              void* d_out, int out_size) {
    const float* x    = (const float*)d_in[0];
    const int*   ei   = (const int*)d_in[1];
    const int*   batch= (const int*)d_in[2];
    const float* W0   = (const float*)d_in[3];
    const float* as0  = (const float*)d_in[4];
    const float* ad0  = (const float*)d_in[5];
    const float* b0   = (const float*)d_in[6];
    const float* Ws   = (const float*)d_in[7];
    const float* asr  = (const float*)d_in[8];
    const float* ads  = (const float*)d_in[9];
    const float* bs   = (const float*)d_in[10];
    const float* lng  = (const float*)d_in[11];
    const float* lnb  = (const float*)d_in[12];
    float* out  = (float*)d_out;
    float* gout = out + (size_t)NN * DD;

    float *hA, *hB;
    __half* hlinh;
    cudaGetSymbolAddress((void**)&hA, g_hA);
    cudaGetSymbolAddress((void**)&hB, g_hB);
    cudaGetSymbolAddress((void**)&hlinh, g_hlinh);
    __nv_bfloat16 *Ahi, *Alo, *Whi, *Wlo;
    cudaGetSymbolAddress((void**)&Ahi, g_Ahi);
    cudaGetSymbolAddress((void**)&Alo, g_Alo);
    cudaGetSymbolAddress((void**)&Whi, g_Whi);
    cudaGetSymbolAddress((void**)&Wlo, g_Wlo);

    cudaFuncSetAttribute(k_gemm_tc, cudaFuncAttributeMaxDynamicSharedMemorySize, SMEM_TC2);

    const int gat_blocks = (NN + 8 * NPW - 1) / (8 * NPW);

    // CSR build + init
    k_zero<<<(NN + 255) / 256, 256>>>(gout, Ws);
    k_count<<<(EE + 255) / 256, 256>>>(ei);
    k_scan_block<<<NB1, 1024>>>();
    k_scan_bsums<<<1, 128>>>();
    k_scan_add<<<(NN + 255) / 256, 256>>>();
    k_fill<<<(EE + 255) / 256, 256>>>(ei);

    // layer 0 (alpha fused into gemm0)
    k_gemm0<<<(NN + 7) / 8, 128>>>(x, W0, as0, ad0, hlinh);
    k_gat<<<gat_blocks, 256>>>(hlinh, nullptr, b0, lng, lnb, hA, 0, 1);

    // layers 1..3
    const float* cur = hA;
    for (int l = 1; l < 4; l++) {
        float* nxt = (l == 3) ? out : ((l & 1) ? hB : hA);
        k_gemm_tc<<<(NN + 127) / 128, 256, SMEM_TC2>>>(
            Ahi, Alo, Whi + (size_t)(l - 1) * DD * DD, Wlo + (size_t)(l - 1) * DD * DD,
            hlinh, asr + (l - 1) * DD, ads + (l - 1) * DD);
        k_gat<<<gat_blocks, 256>>>(hlinh, cur, bs + (l - 1) * DD,
                                   lng + l * DD, lnb + l * DD, nxt, 1,
                                   (l < 3) ? 1 : 0);
        cur = nxt;
    }

    // graph mean pooling
    k_pool<<<(NN + 127) / 128, 128>>>(out, batch, gout);
    k_final<<<GG, 128>>>(gout, batch);
}

// round 10
// speedup vs baseline: 1.0689x; 1.0689x over previous
#include <cuda_runtime.h>
#include <cuda_bf16.h>
#include <cuda_fp16.h>
#include <cstdint>
#include <mma.h>

#define NN 100000
#define EE 1600000
#define HH 4
#define CC 32
#define DD 128
#define GG 64
#define NEG 0.2f
#define NB1 ((NN + 1023) / 1024)

using namespace nvcuda;

// ---------------- device scratch ----------------
__device__ float g_hA[(size_t)NN * DD];
__device__ float g_hB[(size_t)NN * DD];
__device__ __half g_hlinh[(size_t)NN * DD];      // fp16 hlin (gather operand)
__device__ __nv_bfloat16 g_Ahi[(size_t)NN * DD];
__device__ __nv_bfloat16 g_Alo[(size_t)NN * DD];
__device__ __nv_bfloat16 g_Whi[3 * DD * DD];
__device__ __nv_bfloat16 g_Wlo[3 * DD * DD];
__device__ float g_asrc[NN * HH];
__device__ float g_adst[NN * HH];
__device__ int   g_deg[NN];
__device__ int   g_rowptr[NN + 1];
__device__ int   g_cursor[NN];
__device__ int   g_col[EE];
__device__ int   g_bsums[128];

__device__ __forceinline__ float lrelu(float x) { return x > 0.f ? x : NEG * x; }

// ---------------- init (zero + W bf16-split fused) ----------------
__global__ void k_zero(float* __restrict__ gout, const float* __restrict__ Ws) {
    int i = blockIdx.x * blockDim.x + threadIdx.x;
    if (i < NN) g_deg[i] = 0;
    if (i < GG * DD) gout[i] = 0.f;
    if (i < 3 * DD * DD) {
        float f = Ws[i];
        __nv_bfloat16 hi = __float2bfloat16(f);
        g_Whi[i] = hi;
        g_Wlo[i] = __float2bfloat16(f - __bfloat162float(hi));
    }
}

__global__ void k_count(const int* __restrict__ ei) {
    int e = blockIdx.x * blockDim.x + threadIdx.x;
    if (e < EE) atomicAdd(&g_deg[ei[EE + e]], 1);
}

__global__ void k_scan_block() {
    __shared__ int s[1024];
    int i = blockIdx.x * 1024 + threadIdx.x;
    int v = (i < NN) ? g_deg[i] : 0;
    s[threadIdx.x] = v;
    __syncthreads();
    for (int off = 1; off < 1024; off <<= 1) {
        int t = (threadIdx.x >= off) ? s[threadIdx.x - off] : 0;
        __syncthreads();
        s[threadIdx.x] += t;
        __syncthreads();
    }
    if (i < NN) g_rowptr[i] = s[threadIdx.x] - v;
    if (threadIdx.x == 1023) g_bsums[blockIdx.x] = s[1023];
}

__global__ void k_scan_bsums() {
    __shared__ int s[128];
    int t = threadIdx.x;
    int v = (t < NB1) ? g_bsums[t] : 0;
    s[t] = v;
    __syncthreads();
    for (int off = 1; off < 128; off <<= 1) {
        int u = (t >= off) ? s[t - off] : 0;
        __syncthreads();
        s[t] += u;
        __syncthreads();
    }
    if (t < NB1) g_bsums[t] = s[t] - v;
}

__global__ void k_scan_add() {
    int i = blockIdx.x * blockDim.x + threadIdx.x;
    if (i < NN) {
        int v = g_rowptr[i] + g_bsums[i >> 10];
        g_rowptr[i] = v;
        g_cursor[i] = v;
    }
    if (i == 0) g_rowptr[NN] = EE;
}

__global__ void k_fill(const int* __restrict__ ei) {
    int e = blockIdx.x * blockDim.x + threadIdx.x;
    if (e < EE) {
        int src = ei[e];
        int dst = ei[EE + e];
        int pos = atomicAdd(&g_cursor[dst], 1);
        g_col[pos] = src;
    }
}

// ---------------- layer-0 GEMM [NN,7]@[7,128] + fused alpha ----------------
__global__ __launch_bounds__(128) void k_gemm0(const float* __restrict__ x,
                                               const float* __restrict__ W,
                                               const float* __restrict__ aws,
                                               const float* __restrict__ awd,
                                               __half* __restrict__ outh) {
    __shared__ float Ws[7 * 128];
    __shared__ float xs[8 * 7];
    int t = threadIdx.x;
    int w = t >> 5, lane = t & 31;
    for (int i = t; i < 7 * 128; i += 128) Ws[i] = W[i];
    int base = blockIdx.x * 8;
    for (int i = t; i < 8 * 7; i += 128) {
        int nn = base + i / 7;
        xs[i] = (nn < NN) ? x[nn * 7 + (i % 7)] : 0.f;
    }
    float awsv = aws[t], awdv = awd[t];
    __syncthreads();
    for (int j = 0; j < 8; j++) {
        int n = base + j;
        if (n < NN) {
            float s = 0.f;
#pragma unroll
            for (int k = 0; k < 7; k++) s = fmaf(xs[j * 7 + k], Ws[k * 128 + t], s);
            outh[(size_t)n * DD + t] = __float2half(s);
            float ps = s * awsv, pd = s * awdv;
#pragma unroll
            for (int o = 16; o >= 1; o >>= 1) {
                ps += __shfl_xor_sync(0xffffffffu, ps, o);
                pd += __shfl_xor_sync(0xffffffffu, pd, o);
            }
            if (lane == 0) {
                g_asrc[n * 4 + w] = ps;
                g_adst[n * 4 + w] = pd;
            }
        }
    }
}

// ---------------- layers 1-3 GEMM: wmma bf16 split + fused alpha, fp16 output
#define BSTRIDE 136
#define ASTRIDE 40
#define SMEM_TC2 91136

__global__ __launch_bounds__(256, 2)
void k_gemm_tc(const __nv_bfloat16* __restrict__ Ahi, const __nv_bfloat16* __restrict__ Alo,
               const __nv_bfloat16* __restrict__ Whi, const __nv_bfloat16* __restrict__ Wlo,
               __half* __restrict__ Couth,
               const float* __restrict__ aw_src, const float* __restrict__ aw_dst) {
    extern __shared__ char dsm[];
    float* awsS = (float*)dsm;
    float* awdS = (float*)(dsm + 512);
    __nv_bfloat16* Bh = (__nv_bfloat16*)(dsm + 1024);
    __nv_bfloat16* Bl = (__nv_bfloat16*)(dsm + 35840);
    __nv_bfloat16* Ah = (__nv_bfloat16*)(dsm + 70656);
    __nv_bfloat16* Al = (__nv_bfloat16*)(dsm + 80896);
    const int tid = threadIdx.x;
    const int wid = tid >> 5;
    const int lane = tid & 31;
    const int row0 = blockIdx.x * 128;
    const int warp_m = wid & 3;
    const int warp_n = wid >> 2;

    if (tid < 128) {
        awsS[tid] = aw_src[tid];
        awdS[tid] = aw_dst[tid];
    }
    {
        int br = tid >> 1, cb = (tid & 1) * 64;
        const uint4* sh = (const uint4*)&Whi[br * DD + cb];
        const uint4* sl = (const uint4*)&Wlo[br * DD + cb];
        uint4* dh = (uint4*)&Bh[br * BSTRIDE + cb];
        uint4* dl = (uint4*)&Bl[br * BSTRIDE + cb];
#pragma unroll
        for (int i = 0; i < 8; i++) { dh[i] = sh[i]; dl[i] = sl[i]; }
    }
    const int ar = tid >> 1;
    const int akb = (tid & 1) * 16;
    const size_t agrow = (size_t)min(row0 + ar, NN - 1) * DD;
#define LOAD_A(c)                                                             \
    do {                                                                      \
        const uint4* sh_ = (const uint4*)&Ahi[agrow + (c) * 32 + akb];        \
        const uint4* sl_ = (const uint4*)&Alo[agrow + (c) * 32 + akb];        \
        uint4* dh_ = (uint4*)&Ah[ar * ASTRIDE + akb];                         \
        uint4* dl_ = (uint4*)&Al[ar * ASTRIDE + akb];                         \
        dh_[0] = sh_[0]; dh_[1] = sh_[1];                                     \
        dl_[0] = sl_[0]; dl_[1] = sl_[1];                                     \
    } while (0)

    wmma::fragment<wmma::accumulator, 16, 16, 16, float> acc[2][4];
#pragma unroll
    for (int im = 0; im < 2; im++)
#pragma unroll
        for (int in = 0; in < 4; in++) wmma::fill_fragment(acc[im][in], 0.f);

    LOAD_A(0);
    __syncthreads();

#pragma unroll
    for (int c = 0; c < 4; c++) {
#pragma unroll
        for (int ksl = 0; ksl < 2; ksl++) {
            wmma::fragment<wmma::matrix_a, 16, 16, 16, __nv_bfloat16, wmma::row_major> ah[2], al[2];
#pragma unroll
            for (int im = 0; im < 2; im++) {
                wmma::load_matrix_sync(ah[im], &Ah[(warp_m * 32 + im * 16) * ASTRIDE + ksl * 16], ASTRIDE);
                wmma::load_matrix_sync(al[im], &Al[(warp_m * 32 + im * 16) * ASTRIDE + ksl * 16], ASTRIDE);
            }
            const int krow = c * 32 + ksl * 16;
#pragma unroll
            for (int in = 0; in < 4; in++) {
                wmma::fragment<wmma::matrix_b, 16, 16, 16, __nv_bfloat16, wmma::row_major> bh, bl;
                wmma::load_matrix_sync(bh, &Bh[krow * BSTRIDE + warp_n * 64 + in * 16], BSTRIDE);
                wmma::load_matrix_sync(bl, &Bl[krow * BSTRIDE + warp_n * 64 + in * 16], BSTRIDE);
#pragma unroll
                for (int im = 0; im < 2; im++) {
                    wmma::mma_sync(acc[im][in], ah[im], bh, acc[im][in]);
                    wmma::mma_sync(acc[im][in], al[im], bh, acc[im][in]);
                    wmma::mma_sync(acc[im][in], ah[im], bl, acc[im][in]);
                }
            }
        }
        __syncthreads();
        if (c < 3) {
            LOAD_A(c + 1);
            __syncthreads();
        }
    }

    float* osm = (float*)(dsm + 1024);
#pragma unroll
    for (int im = 0; im < 2; im++)
#pragma unroll
        for (int in = 0; in < 4; in++)
            wmma::store_matrix_sync(&osm[(warp_m * 32 + im * 16) * BSTRIDE + warp_n * 64 + in * 16],
                                    acc[im][in], BSTRIDE, wmma::mem_row_major);
    __syncthreads();

    if (wid < 4) {
        int r = wid * 32 + lane;
        int grow = row0 + r;
        if (grow < NN) {
#pragma unroll
            for (int b = 0; b < 4; b++) {
                float asum = 0.f, dsum = 0.f;
#pragma unroll
                for (int i = 0; i < 32; i++) {
                    float v = osm[r * BSTRIDE + b * 32 + i];
                    asum = fmaf(v, awsS[b * 32 + i], asum);
                    dsum = fmaf(v, awdS[b * 32 + i], dsum);
                }
                g_asrc[grow * 4 + b] = asum;
                g_adst[grow * 4 + b] = dsum;
            }
        }
    }
    for (int idx = tid; idx < 128 * 32; idx += 256) {
        int r = idx >> 5;
        int c4 = (idx & 31) << 2;
        if (row0 + r < NN) {
            float4 v = *(const float4*)&osm[r * BSTRIDE + c4];
            __half2 h0 = __floats2half2_rn(v.x, v.y);
            __half2 h1 = __floats2half2_rn(v.z, v.w);
            uint2 o;
            o.x = *(uint32_t*)&h0;
            o.y = *(uint32_t*)&h1;
            *(uint2*)&Couth[(size_t)(row0 + r) * DD + c4] = o;
        }
    }
#undef LOAD_A
}

// ---------------- fused single-pass GAT layer (R8 shape; byte-offset staging,
// unroll 8). One warp per dst node; lane owns 4 channels; one edge per iter.
__global__ __launch_bounds__(256) void k_gat(const __half* __restrict__ hlin,
                                             const float* __restrict__ hprev,
                                             const float* __restrict__ bias,
                                             const float* __restrict__ gam,
                                             const float* __restrict__ bet,
                                             float* __restrict__ outp, int residual,
                                             int wbf) {
    __shared__ float es[8][32][8];
    int n = (blockIdx.x * blockDim.x + threadIdx.x) >> 5;
    if (n >= NN) return;
    const int lane = threadIdx.x & 31;
    const int wslot = (threadIdx.x >> 5) & 7;
    const int hd = lane >> 3;
    const int rs = g_rowptr[n], re = g_rowptr[n + 1];

    float4 ad4 = *(const float4*)&g_adst[n * 4];
    float4 as4 = *(const float4*)&g_asrc[n * 4];
    const float ad0 = ad4.x, ad1 = ad4.y, ad2 = ad4.z, ad3 = ad4.w;

    float w0 = __expf(lrelu(as4.x + ad0));
    float w1 = __expf(lrelu(as4.y + ad1));
    float w2 = __expf(lrelu(as4.z + ad2));
    float w3 = __expf(lrelu(as4.w + ad3));
    float z0 = (lane == 0) ? w0 : 0.f;
    float z1 = (lane == 0) ? w1 : 0.f;
    float z2 = (lane == 0) ? w2 : 0.f;
    float z3 = (lane == 0) ? w3 : 0.f;

    float wslf = (hd == 0) ? w0 : (hd == 1) ? w1 : (hd == 2) ? w2 : w3;
    const char* hb = (const char*)hlin + lane * 8;   // lane-offset base
    uint2 sp = *(const uint2*)(hb + (size_t)n * 256);
    float2 sf01 = __half22float2(*(__half2*)&sp.x);
    float2 sf23 = __half22float2(*(__half2*)&sp.y);
    float a0 = sf01.x * wslf, a1 = sf01.y * wslf, a2 = sf23.x * wslf, a3 = sf23.y * wslf;

    const float2* ep = (const float2*)&es[wslot][0][hd * 2];

    for (int c = rs; c < re; c += 32) {
        int cnt = re - c;
        if (cnt > 32) cnt = 32;
        if (lane < cnt) {
            int s = __ldg(&g_col[c + lane]);
            float4 a = *(const float4*)&g_asrc[s * 4];
            float e0 = __expf(lrelu(a.x + ad0));
            float e1 = __expf(lrelu(a.y + ad1));
            float e2 = __expf(lrelu(a.z + ad2));
            float e3 = __expf(lrelu(a.w + ad3));
            z0 += e0; z1 += e1; z2 += e2; z3 += e3;
            float ov = __int_as_float(s << 8);        // byte offset = s*256
            *(float4*)&es[wslot][lane][0] = make_float4(e0, ov, e1, ov);
            *(float4*)&es[wslot][lane][4] = make_float4(e2, ov, e3, ov);
        }
        __syncwarp();
#pragma unroll 8
        for (int j = 0; j < cnt; j++) {
            float2 wsj = ep[j * 4];            // (e_hd, byte_off) in one LDS.64
            float wj = wsj.x;
            uint2 p = *(const uint2*)(hb + __float_as_int(wsj.y));
            float2 f01 = __half22float2(*(__half2*)&p.x);
            float2 f23 = __half22float2(*(__half2*)&p.y);
            a0 = fmaf(f01.x, wj, a0);
            a1 = fmaf(f01.y, wj, a1);
            a2 = fmaf(f23.x, wj, a2);
            a3 = fmaf(f23.y, wj, a3);
        }
        __syncwarp();
    }
#pragma unroll
    for (int o = 16; o >= 1; o >>= 1) {
        z0 += __shfl_xor_sync(0xffffffffu, z0, o);
        z1 += __shfl_xor_sync(0xffffffffu, z1, o);
        z2 += __shfl_xor_sync(0xffffffffu, z2, o);
        z3 += __shfl_xor_sync(0xffffffffu, z3, o);
    }
    float zh = (hd == 0) ? z0 : (hd == 1) ? z1 : (hd == 2) ? z2 : z3;
    float invz = 1.f / (zh + 1e-16f);
    a0 *= invz; a1 *= invz; a2 *= invz; a3 *= invz;

    float4 bv = *(const float4*)&bias[lane * 4];
    a0 += bv.x; a1 += bv.y; a2 += bv.z; a3 += bv.w;
    float sm = a0 + a1 + a2 + a3;
#pragma unroll
    for (int o = 16; o >= 1; o >>= 1) sm += __shfl_xor_sync(0xffffffffu, sm, o);
    float mean = sm * (1.f / DD);
    float d0 = a0 - mean, d1 = a1 - mean, d2 = a2 - mean, d3 = a3 - mean;
    float sq = d0 * d0 + d1 * d1 + d2 * d2 + d3 * d3;
#pragma unroll
    for (int o = 16; o >= 1; o >>= 1) sq += __shfl_xor_sync(0xffffffffu, sq, o);
    float rstd = rsqrtf(sq * (1.f / DD) + 1e-5f);
    float4 gv = *(const float4*)&gam[lane * 4];
    float4 bev = *(const float4*)&bet[lane * 4];
    float v0 = d0 * rstd * gv.x + bev.x;
    float v1 = d1 * rstd * gv.y + bev.y;
    float v2 = d2 * rstd * gv.z + bev.z;
    float v3 = d3 * rstd * gv.w + bev.w;
    v0 = v0 > 0.f ? v0 : __expf(v0) - 1.f;
    v1 = v1 > 0.f ? v1 : __expf(v1) - 1.f;
    v2 = v2 > 0.f ? v2 : __expf(v2) - 1.f;
    v3 = v3 > 0.f ? v3 : __expf(v3) - 1.f;
    if (residual) {
        float4 pv = *(const float4*)&hprev[(size_t)n * DD + lane * 4];
        v0 += pv.x; v1 += pv.y; v2 += pv.z; v3 += pv.w;
    }
    *(float4*)&outp[(size_t)n * DD + lane * 4] = make_float4(v0, v1, v2, v3);

    if (wbf) {
        __nv_bfloat16 h0 = __float2bfloat16(v0);
        __nv_bfloat16 h1 = __float2bfloat16(v1);
        __nv_bfloat16 h2 = __float2bfloat16(v2);
        __nv_bfloat16 h3 = __float2bfloat16(v3);
        __nv_bfloat16 l0 = __float2bfloat16(v0 - __bfloat162float(h0));
        __nv_bfloat16 l1 = __float2bfloat16(v1 - __bfloat162float(h1));
        __nv_bfloat16 l2 = __float2bfloat16(v2 - __bfloat162float(h2));
        __nv_bfloat16 l3 = __float2bfloat16(v3 - __bfloat162float(h3));
        uint2 ph, pl;
        ph.x = (uint32_t)__bfloat16_as_ushort(h0) | ((uint32_t)__bfloat16_as_ushort(h1) << 16);
        ph.y = (uint32_t)__bfloat16_as_ushort(h2) | ((uint32_t)__bfloat16_as_ushort(h3) << 16);
        pl.x = (uint32_t)__bfloat16_as_ushort(l0) | ((uint32_t)__bfloat16_as_ushort(l1) << 16);
        pl.y = (uint32_t)__bfloat16_as_ushort(l2) | ((uint32_t)__bfloat16_as_ushort(l3) << 16);
        *(uint2*)&g_Ahi[(size_t)n * DD + lane * 4] = ph;
        *(uint2*)&g_Alo[(size_t)n * DD + lane * 4] = pl;
    }
}

// ---------------- graph pooling ----------------
__global__ __launch_bounds__(128) void k_pool(const float* __restrict__ ne,
                                              const int* __restrict__ batch,
                                              float* __restrict__ gout) {
    int base = blockIdx.x * 128;
    if (base >= NN) return;
    int d = threadIdx.x;
    int end = base + 128;
    if (end > NN) end = NN;
    float acc = 0.f;
    int cg = __ldg(&batch[base]);
    for (int n = base; n < end; n++) {
        int gidx = __ldg(&batch[n]);
        if (gidx != cg) {
            atomicAdd(&gout[cg * DD + d], acc);
            acc = 0.f;
            cg = gidx;
        }
        acc += ne[(size_t)n * DD + d];
    }
    atomicAdd(&gout[cg * DD + d], acc);
}

// per-graph counts via binary search on sorted batch
__global__ void k_final(float* __restrict__ gout, const int* __restrict__ batch) {
    int g = blockIdx.x;
    int d = threadIdx.x;
    __shared__ int cnt_s;
    if (d == 0) {
        int lo = 0, hi = NN;
        while (lo < hi) { int m = (lo + hi) >> 1; if (batch[m] < g) lo = m + 1; else hi = m; }
        int lb = lo;
        lo = lb; hi = NN;
        while (lo < hi) { int m = (lo + hi) >> 1; if (batch[m] < g + 1) lo = m + 1; else hi = m; }
        cnt_s = lo - lb;
    }
    __syncthreads();
    gout[g * DD + d] /= fmaxf((float)cnt_s, 1.f);
}

// ---------------- host launch ----------------
extern "C" void kernel_launch(void* const* d_in, const int* in_sizes, int n_in,
                              void* d_out, int out_size) {
    const float* x    = (const float*)d_in[0];
    const int*   ei   = (const int*)d_in[1];
    const int*   batch= (const int*)d_in[2];
    const float* W0   = (const float*)d_in[3];
    const float* as0  = (const float*)d_in[4];
    const float* ad0  = (const float*)d_in[5];
    const float* b0   = (const float*)d_in[6];
    const float* Ws   = (const float*)d_in[7];
    const float* asr  = (const float*)d_in[8];
    const float* ads  = (const float*)d_in[9];
    const float* bs   = (const float*)d_in[10];
    const float* lng  = (const float*)d_in[11];
    const float* lnb  = (const float*)d_in[12];
    float* out  = (float*)d_out;
    float* gout = out + (size_t)NN * DD;

    float *hA, *hB;
    __half* hlinh;
    cudaGetSymbolAddress((void**)&hA, g_hA);
    cudaGetSymbolAddress((void**)&hB, g_hB);
    cudaGetSymbolAddress((void**)&hlinh, g_hlinh);
    __nv_bfloat16 *Ahi, *Alo, *Whi, *Wlo;
    cudaGetSymbolAddress((void**)&Ahi, g_Ahi);
    cudaGetSymbolAddress((void**)&Alo, g_Alo);
    cudaGetSymbolAddress((void**)&Whi, g_Whi);
    cudaGetSymbolAddress((void**)&Wlo, g_Wlo);

    cudaFuncSetAttribute(k_gemm_tc, cudaFuncAttributeMaxDynamicSharedMemorySize, SMEM_TC2);

    // CSR build + init
    k_zero<<<(NN + 255) / 256, 256>>>(gout, Ws);
    k_count<<<(EE + 255) / 256, 256>>>(ei);
    k_scan_block<<<NB1, 1024>>>();
    k_scan_bsums<<<1, 128>>>();
    k_scan_add<<<(NN + 255) / 256, 256>>>();
    k_fill<<<(EE + 255) / 256, 256>>>(ei);

    // layer 0 (alpha fused into gemm0)
    k_gemm0<<<(NN + 7) / 8, 128>>>(x, W0, as0, ad0, hlinh);
    k_gat<<<(NN * 32 + 255) / 256, 256>>>(hlinh, nullptr, b0, lng, lnb, hA, 0, 1);

    // layers 1..3
    const float* cur = hA;
    for (int l = 1; l < 4; l++) {
        float* nxt = (l == 3) ? out : ((l & 1) ? hB : hA);
        k_gemm_tc<<<(NN + 127) / 128, 256, SMEM_TC2>>>(
            Ahi, Alo, Whi + (size_t)(l - 1) * DD * DD, Wlo + (size_t)(l - 1) * DD * DD,
            hlinh, asr + (l - 1) * DD, ads + (l - 1) * DD);
        k_gat<<<(NN * 32 + 255) / 256, 256>>>(hlinh, cur, bs + (l - 1) * DD,
                                              lng + l * DD, lnb + l * DD, nxt, 1,
                                              (l < 3) ? 1 : 0);
        cur = nxt;
    }

    // graph mean pooling
    k_pool<<<(NN + 127) / 128, 128>>>(out, batch, gout);
    k_final<<<GG, 128>>>(gout, batch);
}

// round 11
// speedup vs baseline: 1.0731x; 1.0039x over previous
#include <cuda_runtime.h>
#include <cuda_bf16.h>
#include <cuda_fp16.h>
#include <cstdint>
#include <mma.h>

#define NN 100000
#define EE 1600000
#define HH 4
#define CC 32
#define DD 128
#define GG 64
#define NEG 0.2f
#define NB1 ((NN + 1023) / 1024)

using namespace nvcuda;

// ---------------- device scratch ----------------
__device__ float g_hA[(size_t)NN * DD];
__device__ float g_hB[(size_t)NN * DD];
__device__ __half g_hlinh[(size_t)NN * DD];      // fp16 hlin (gather operand)
__device__ __nv_bfloat16 g_Ahi[(size_t)NN * DD];
__device__ __nv_bfloat16 g_Alo[(size_t)NN * DD];
__device__ __nv_bfloat16 g_Whi[3 * DD * DD];
__device__ __nv_bfloat16 g_Wlo[3 * DD * DD];
__device__ float g_asrc[NN * HH];
__device__ float g_adst[NN * HH];
__device__ float g_ew[(size_t)EE * 4];           // per-edge softmax weights (per head)
__device__ int   g_deg[NN];
__device__ int   g_rowptr[NN + 1];
__device__ int   g_cursor[NN];
__device__ int   g_colb[EE];                     // src << 8 (byte offset into hlin)
__device__ int   g_dstp[EE];                     // dst per CSR slot
__device__ int   g_bsums[128];

__device__ __forceinline__ float lrelu(float x) { return x > 0.f ? x : NEG * x; }

// ---------------- init (zero + W bf16-split fused) ----------------
__global__ void k_zero(float* __restrict__ gout, const float* __restrict__ Ws) {
    int i = blockIdx.x * blockDim.x + threadIdx.x;
    if (i < NN) g_deg[i] = 0;
    if (i < GG * DD) gout[i] = 0.f;
    if (i < 3 * DD * DD) {
        float f = Ws[i];
        __nv_bfloat16 hi = __float2bfloat16(f);
        g_Whi[i] = hi;
        g_Wlo[i] = __float2bfloat16(f - __bfloat162float(hi));
    }
}

__global__ void k_count(const int* __restrict__ ei) {
    int e = blockIdx.x * blockDim.x + threadIdx.x;
    if (e < EE) atomicAdd(&g_deg[ei[EE + e]], 1);
}

__global__ void k_scan_block() {
    __shared__ int s[1024];
    int i = blockIdx.x * 1024 + threadIdx.x;
    int v = (i < NN) ? g_deg[i] : 0;
    s[threadIdx.x] = v;
    __syncthreads();
    for (int off = 1; off < 1024; off <<= 1) {
        int t = (threadIdx.x >= off) ? s[threadIdx.x - off] : 0;
        __syncthreads();
        s[threadIdx.x] += t;
        __syncthreads();
    }
    if (i < NN) g_rowptr[i] = s[threadIdx.x] - v;
    if (threadIdx.x == 1023) g_bsums[blockIdx.x] = s[1023];
}

__global__ void k_scan_bsums() {
    __shared__ int s[128];
    int t = threadIdx.x;
    int v = (t < NB1) ? g_bsums[t] : 0;
    s[t] = v;
    __syncthreads();
    for (int off = 1; off < 128; off <<= 1) {
        int u = (t >= off) ? s[t - off] : 0;
        __syncthreads();
        s[t] += u;
        __syncthreads();
    }
    if (t < NB1) g_bsums[t] = s[t] - v;
}

__global__ void k_scan_add() {
    int i = blockIdx.x * blockDim.x + threadIdx.x;
    if (i < NN) {
        int v = g_rowptr[i] + g_bsums[i >> 10];
        g_rowptr[i] = v;
        g_cursor[i] = v;
    }
    if (i == 0) g_rowptr[NN] = EE;
}

__global__ void k_fill(const int* __restrict__ ei) {
    int e = blockIdx.x * blockDim.x + threadIdx.x;
    if (e < EE) {
        int src = ei[e];
        int dst = ei[EE + e];
        int pos = atomicAdd(&g_cursor[dst], 1);
        g_colb[pos] = src << 8;      // byte offset: src * 256
        g_dstp[pos] = dst;
    }
}

// ---------------- edge-weight pre-pass (per layer) ----------------
__global__ __launch_bounds__(256) void k_ew() {
    int e = blockIdx.x * blockDim.x + threadIdx.x;
    if (e >= EE) return;
    int off = g_colb[e];                               // s << 8
    int d = g_dstp[e];
    const float4 a = *(const float4*)((const char*)g_asrc + (off >> 4));  // s*16 bytes
    const float4 ad = *(const float4*)&g_adst[d * 4];
    float4 w;
    w.x = __expf(lrelu(a.x + ad.x));
    w.y = __expf(lrelu(a.y + ad.y));
    w.z = __expf(lrelu(a.z + ad.z));
    w.w = __expf(lrelu(a.w + ad.w));
    *(float4*)&g_ew[(size_t)e * 4] = w;
}

// ---------------- layer-0 GEMM [NN,7]@[7,128] + fused alpha ----------------
__global__ __launch_bounds__(128) void k_gemm0(const float* __restrict__ x,
                                               const float* __restrict__ W,
                                               const float* __restrict__ aws,
                                               const float* __restrict__ awd,
                                               __half* __restrict__ outh) {
    __shared__ float Ws[7 * 128];
    __shared__ float xs[8 * 7];
    int t = threadIdx.x;
    int w = t >> 5, lane = t & 31;
    for (int i = t; i < 7 * 128; i += 128) Ws[i] = W[i];
    int base = blockIdx.x * 8;
    for (int i = t; i < 8 * 7; i += 128) {
        int nn = base + i / 7;
        xs[i] = (nn < NN) ? x[nn * 7 + (i % 7)] : 0.f;
    }
    float awsv = aws[t], awdv = awd[t];
    __syncthreads();
    for (int j = 0; j < 8; j++) {
        int n = base + j;
        if (n < NN) {
            float s = 0.f;
#pragma unroll
            for (int k = 0; k < 7; k++) s = fmaf(xs[j * 7 + k], Ws[k * 128 + t], s);
            outh[(size_t)n * DD + t] = __float2half(s);
            float ps = s * awsv, pd = s * awdv;
#pragma unroll
            for (int o = 16; o >= 1; o >>= 1) {
                ps += __shfl_xor_sync(0xffffffffu, ps, o);
                pd += __shfl_xor_sync(0xffffffffu, pd, o);
            }
            if (lane == 0) {
                g_asrc[n * 4 + w] = ps;
                g_adst[n * 4 + w] = pd;
            }
        }
    }
}

// ---------------- layers 1-3 GEMM: wmma bf16 split + fused alpha, fp16 output
#define BSTRIDE 136
#define ASTRIDE 40
#define SMEM_TC2 91136

__global__ __launch_bounds__(256, 2)
void k_gemm_tc(const __nv_bfloat16* __restrict__ Ahi, const __nv_bfloat16* __restrict__ Alo,
               const __nv_bfloat16* __restrict__ Whi, const __nv_bfloat16* __restrict__ Wlo,
               __half* __restrict__ Couth,
               const float* __restrict__ aw_src, const float* __restrict__ aw_dst) {
    extern __shared__ char dsm[];
    float* awsS = (float*)dsm;
    float* awdS = (float*)(dsm + 512);
    __nv_bfloat16* Bh = (__nv_bfloat16*)(dsm + 1024);
    __nv_bfloat16* Bl = (__nv_bfloat16*)(dsm + 35840);
    __nv_bfloat16* Ah = (__nv_bfloat16*)(dsm + 70656);
    __nv_bfloat16* Al = (__nv_bfloat16*)(dsm + 80896);
    const int tid = threadIdx.x;
    const int wid = tid >> 5;
    const int lane = tid & 31;
    const int row0 = blockIdx.x * 128;
    const int warp_m = wid & 3;
    const int warp_n = wid >> 2;

    if (tid < 128) {
        awsS[tid] = aw_src[tid];
        awdS[tid] = aw_dst[tid];
    }
    {
        int br = tid >> 1, cb = (tid & 1) * 64;
        const uint4* sh = (const uint4*)&Whi[br * DD + cb];
        const uint4* sl = (const uint4*)&Wlo[br * DD + cb];
        uint4* dh = (uint4*)&Bh[br * BSTRIDE + cb];
        uint4* dl = (uint4*)&Bl[br * BSTRIDE + cb];
#pragma unroll
        for (int i = 0; i < 8; i++) { dh[i] = sh[i]; dl[i] = sl[i]; }
    }
    const int ar = tid >> 1;
    const int akb = (tid & 1) * 16;
    const size_t agrow = (size_t)min(row0 + ar, NN - 1) * DD;
#define LOAD_A(c)                                                             \
    do {                                                                      \
        const uint4* sh_ = (const uint4*)&Ahi[agrow + (c) * 32 + akb];        \
        const uint4* sl_ = (const uint4*)&Alo[agrow + (c) * 32 + akb];        \
        uint4* dh_ = (uint4*)&Ah[ar * ASTRIDE + akb];                         \
        uint4* dl_ = (uint4*)&Al[ar * ASTRIDE + akb];                         \
        dh_[0] = sh_[0]; dh_[1] = sh_[1];                                     \
        dl_[0] = sl_[0]; dl_[1] = sl_[1];                                     \
    } while (0)

    wmma::fragment<wmma::accumulator, 16, 16, 16, float> acc[2][4];
#pragma unroll
    for (int im = 0; im < 2; im++)
#pragma unroll
        for (int in = 0; in < 4; in++) wmma::fill_fragment(acc[im][in], 0.f);

    LOAD_A(0);
    __syncthreads();

#pragma unroll
    for (int c = 0; c < 4; c++) {
#pragma unroll
        for (int ksl = 0; ksl < 2; ksl++) {
            wmma::fragment<wmma::matrix_a, 16, 16, 16, __nv_bfloat16, wmma::row_major> ah[2], al[2];
#pragma unroll
            for (int im = 0; im < 2; im++) {
                wmma::load_matrix_sync(ah[im], &Ah[(warp_m * 32 + im * 16) * ASTRIDE + ksl * 16], ASTRIDE);
                wmma::load_matrix_sync(al[im], &Al[(warp_m * 32 + im * 16) * ASTRIDE + ksl * 16], ASTRIDE);
            }
            const int krow = c * 32 + ksl * 16;
#pragma unroll
            for (int in = 0; in < 4; in++) {
                wmma::fragment<wmma::matrix_b, 16, 16, 16, __nv_bfloat16, wmma::row_major> bh, bl;
                wmma::load_matrix_sync(bh, &Bh[krow * BSTRIDE + warp_n * 64 + in * 16], BSTRIDE);
                wmma::load_matrix_sync(bl, &Bl[krow * BSTRIDE + warp_n * 64 + in * 16], BSTRIDE);
#pragma unroll
                for (int im = 0; im < 2; im++) {
                    wmma::mma_sync(acc[im][in], ah[im], bh, acc[im][in]);
                    wmma::mma_sync(acc[im][in], al[im], bh, acc[im][in]);
                    wmma::mma_sync(acc[im][in], ah[im], bl, acc[im][in]);
                }
            }
        }
        __syncthreads();
        if (c < 3) {
            LOAD_A(c + 1);
            __syncthreads();
        }
    }

    float* osm = (float*)(dsm + 1024);
#pragma unroll
    for (int im = 0; im < 2; im++)
#pragma unroll
        for (int in = 0; in < 4; in++)
            wmma::store_matrix_sync(&osm[(warp_m * 32 + im * 16) * BSTRIDE + warp_n * 64 + in * 16],
                                    acc[im][in], BSTRIDE, wmma::mem_row_major);
    __syncthreads();

    if (wid < 4) {
        int r = wid * 32 + lane;
        int grow = row0 + r;
        if (grow < NN) {
#pragma unroll
            for (int b = 0; b < 4; b++) {
                float asum = 0.f, dsum = 0.f;
#pragma unroll
                for (int i = 0; i < 32; i++) {
                    float v = osm[r * BSTRIDE + b * 32 + i];
                    asum = fmaf(v, awsS[b * 32 + i], asum);
                    dsum = fmaf(v, awdS[b * 32 + i], dsum);
                }
                g_asrc[grow * 4 + b] = asum;
                g_adst[grow * 4 + b] = dsum;
            }
        }
    }
    for (int idx = tid; idx < 128 * 32; idx += 256) {
        int r = idx >> 5;
        int c4 = (idx & 31) << 2;
        if (row0 + r < NN) {
            float4 v = *(const float4*)&osm[r * BSTRIDE + c4];
            __half2 h0 = __floats2half2_rn(v.x, v.y);
            __half2 h1 = __floats2half2_rn(v.z, v.w);
            uint2 o;
            o.x = *(uint32_t*)&h0;
            o.y = *(uint32_t*)&h1;
            *(uint2*)&Couth[(size_t)(row0 + r) * DD + c4] = o;
        }
    }
#undef LOAD_A
}

// ---------------- fused GAT aggregate layer (weights precomputed by k_ew)
// One warp per dst node; lane owns 4 channels; no smem, no syncwarp, no z-shfl.
__global__ __launch_bounds__(256) void k_gat(const __half* __restrict__ hlin,
                                             const float* __restrict__ hprev,
                                             const float* __restrict__ bias,
                                             const float* __restrict__ gam,
                                             const float* __restrict__ bet,
                                             float* __restrict__ outp, int residual,
                                             int wbf) {
    int n = (blockIdx.x * blockDim.x + threadIdx.x) >> 5;
    if (n >= NN) return;
    const int lane = threadIdx.x & 31;
    const int hd = lane >> 3;
    const int rs = g_rowptr[n], re = g_rowptr[n + 1];

    float4 ad4 = *(const float4*)&g_adst[n * 4];
    float4 as4 = *(const float4*)&g_asrc[n * 4];

    // self-loop weight for my head
    float wslf;
    {
        float lx = (hd == 0) ? (as4.x + ad4.x) : (hd == 1) ? (as4.y + ad4.y)
                 : (hd == 2) ? (as4.z + ad4.z) : (as4.w + ad4.w);
        wslf = __expf(lrelu(lx));
    }
    float z = wslf;

    const char* hb = (const char*)hlin + lane * 8;   // lane-offset base
    uint2 sp = *(const uint2*)(hb + (size_t)n * 256);
    float2 sf01 = __half22float2(*(__half2*)&sp.x);
    float2 sf23 = __half22float2(*(__half2*)&sp.y);
    float a0 = sf01.x * wslf, a1 = sf01.y * wslf, a2 = sf23.x * wslf, a3 = sf23.y * wslf;

    const float* ewp = g_ew + hd;                    // per-head weight base

#pragma unroll 8
    for (int e = rs; e < re; e++) {
        int off = __ldg(&g_colb[e]);                 // uniform broadcast (L1)
        float wj = __ldg(&ewp[(size_t)e * 4]);       // uniform-ish (L1)
        uint2 p = *(const uint2*)(hb + off);
        float2 f01 = __half22float2(*(__half2*)&p.x);
        float2 f23 = __half22float2(*(__half2*)&p.y);
        a0 = fmaf(f01.x, wj, a0);
        a1 = fmaf(f01.y, wj, a1);
        a2 = fmaf(f23.x, wj, a2);
        a3 = fmaf(f23.y, wj, a3);
        z += wj;
    }
    float invz = 1.f / (z + 1e-16f);                 // identical across my head group
    a0 *= invz; a1 *= invz; a2 *= invz; a3 *= invz;

    float4 bv = *(const float4*)&bias[lane * 4];
    a0 += bv.x; a1 += bv.y; a2 += bv.z; a3 += bv.w;
    float sm = a0 + a1 + a2 + a3;
#pragma unroll
    for (int o = 16; o >= 1; o >>= 1) sm += __shfl_xor_sync(0xffffffffu, sm, o);
    float mean = sm * (1.f / DD);
    float d0 = a0 - mean, d1 = a1 - mean, d2 = a2 - mean, d3 = a3 - mean;
    float sq = d0 * d0 + d1 * d1 + d2 * d2 + d3 * d3;
#pragma unroll
    for (int o = 16; o >= 1; o >>= 1) sq += __shfl_xor_sync(0xffffffffu, sq, o);
    float rstd = rsqrtf(sq * (1.f / DD) + 1e-5f);
    float4 gv = *(const float4*)&gam[lane * 4];
    float4 bev = *(const float4*)&bet[lane * 4];
    float v0 = d0 * rstd * gv.x + bev.x;
    float v1 = d1 * rstd * gv.y + bev.y;
    float v2 = d2 * rstd * gv.z + bev.z;
    float v3 = d3 * rstd * gv.w + bev.w;
    v0 = v0 > 0.f ? v0 : __expf(v0) - 1.f;
    v1 = v1 > 0.f ? v1 : __expf(v1) - 1.f;
    v2 = v2 > 0.f ? v2 : __expf(v2) - 1.f;
    v3 = v3 > 0.f ? v3 : __expf(v3) - 1.f;
    if (residual) {
        float4 pv = *(const float4*)&hprev[(size_t)n * DD + lane * 4];
        v0 += pv.x; v1 += pv.y; v2 += pv.z; v3 += pv.w;
    }
    *(float4*)&outp[(size_t)n * DD + lane * 4] = make_float4(v0, v1, v2, v3);

    if (wbf) {
        __nv_bfloat16 h0 = __float2bfloat16(v0);
        __nv_bfloat16 h1 = __float2bfloat16(v1);
        __nv_bfloat16 h2 = __float2bfloat16(v2);
        __nv_bfloat16 h3 = __float2bfloat16(v3);
        __nv_bfloat16 l0 = __float2bfloat16(v0 - __bfloat162float(h0));
        __nv_bfloat16 l1 = __float2bfloat16(v1 - __bfloat162float(h1));
        __nv_bfloat16 l2 = __float2bfloat16(v2 - __bfloat162float(h2));
        __nv_bfloat16 l3 = __float2bfloat16(v3 - __bfloat162float(h3));
        uint2 ph, pl;
        ph.x = (uint32_t)__bfloat16_as_ushort(h0) | ((uint32_t)__bfloat16_as_ushort(h1) << 16);
        ph.y = (uint32_t)__bfloat16_as_ushort(h2) | ((uint32_t)__bfloat16_as_ushort(h3) << 16);
        pl.x = (uint32_t)__bfloat16_as_ushort(l0) | ((uint32_t)__bfloat16_as_ushort(l1) << 16);
        pl.y = (uint32_t)__bfloat16_as_ushort(l2) | ((uint32_t)__bfloat16_as_ushort(l3) << 16);
        *(uint2*)&g_Ahi[(size_t)n * DD + lane * 4] = ph;
        *(uint2*)&g_Alo[(size_t)n * DD + lane * 4] = pl;
    }
}

// ---------------- graph pooling ----------------
__global__ __launch_bounds__(128) void k_pool(const float* __restrict__ ne,
                                              const int* __restrict__ batch,
                                              float* __restrict__ gout) {
    int base = blockIdx.x * 128;
    if (base >= NN) return;
    int d = threadIdx.x;
    int end = base + 128;
    if (end > NN) end = NN;
    float acc = 0.f;
    int cg = __ldg(&batch[base]);
    for (int n = base; n < end; n++) {
        int gidx = __ldg(&batch[n]);
        if (gidx != cg) {
            atomicAdd(&gout[cg * DD + d], acc);
            acc = 0.f;
            cg = gidx;
        }
        acc += ne[(size_t)n * DD + d];
    }
    atomicAdd(&gout[cg * DD + d], acc);
}

// per-graph counts via binary search on sorted batch
__global__ void k_final(float* __restrict__ gout, const int* __restrict__ batch) {
    int g = blockIdx.x;
    int d = threadIdx.x;
    __shared__ int cnt_s;
    if (d == 0) {
        int lo = 0, hi = NN;
        while (lo < hi) { int m = (lo + hi) >> 1; if (batch[m] < g) lo = m + 1; else hi = m; }
        int lb = lo;
        lo = lb; hi = NN;
        while (lo < hi) { int m = (lo + hi) >> 1; if (batch[m] < g + 1) lo = m + 1; else hi = m; }
        cnt_s = lo - lb;
    }
    __syncthreads();
    gout[g * DD + d] /= fmaxf((float)cnt_s, 1.f);
}

// ---------------- host launch ----------------
extern "C" void kernel_launch(void* const* d_in, const int* in_sizes, int n_in,
                              void* d_out, int out_size) {
    const float* x    = (const float*)d_in[0];
    const int*   ei   = (const int*)d_in[1];
    const int*   batch= (const int*)d_in[2];
    const float* W0   = (const float*)d_in[3];
    const float* as0  = (const float*)d_in[4];
    const float* ad0  = (const float*)d_in[5];
    const float* b0   = (const float*)d_in[6];
    const float* Ws   = (const float*)d_in[7];
    const float* asr  = (const float*)d_in[8];
    const float* ads  = (const float*)d_in[9];
    const float* bs   = (const float*)d_in[10];
    const float* lng  = (const float*)d_in[11];
    const float* lnb  = (const float*)d_in[12];
    float* out  = (float*)d_out;
    float* gout = out + (size_t)NN * DD;

    float *hA, *hB;
    __half* hlinh;
    cudaGetSymbolAddress((void**)&hA, g_hA);
    cudaGetSymbolAddress((void**)&hB, g_hB);
    cudaGetSymbolAddress((void**)&hlinh, g_hlinh);
    __nv_bfloat16 *Ahi, *Alo, *Whi, *Wlo;
    cudaGetSymbolAddress((void**)&Ahi, g_Ahi);
    cudaGetSymbolAddress((void**)&Alo, g_Alo);
    cudaGetSymbolAddress((void**)&Whi, g_Whi);
    cudaGetSymbolAddress((void**)&Wlo, g_Wlo);

    cudaFuncSetAttribute(k_gemm_tc, cudaFuncAttributeMaxDynamicSharedMemorySize, SMEM_TC2);

    // CSR build + init
    k_zero<<<(NN + 255) / 256, 256>>>(gout, Ws);
    k_count<<<(EE + 255) / 256, 256>>>(ei);
    k_scan_block<<<NB1, 1024>>>();
    k_scan_bsums<<<1, 128>>>();
    k_scan_add<<<(NN + 255) / 256, 256>>>();
    k_fill<<<(EE + 255) / 256, 256>>>(ei);

    // layer 0 (alpha fused into gemm0; edge weights precomputed)
    k_gemm0<<<(NN + 7) / 8, 128>>>(x, W0, as0, ad0, hlinh);
    k_ew<<<(EE + 255) / 256, 256>>>();
    k_gat<<<(NN * 32 + 255) / 256, 256>>>(hlinh, nullptr, b0, lng, lnb, hA, 0, 1);

    // layers 1..3
    const float* cur = hA;
    for (int l = 1; l < 4; l++) {
        float* nxt = (l == 3) ? out : ((l & 1) ? hB : hA);
        k_gemm_tc<<<(NN + 127) / 128, 256, SMEM_TC2>>>(
            Ahi, Alo, Whi + (size_t)(l - 1) * DD * DD, Wlo + (size_t)(l - 1) * DD * DD,
            hlinh, asr + (l - 1) * DD, ads + (l - 1) * DD);
        k_ew<<<(EE + 255) / 256, 256>>>();
        k_gat<<<(NN * 32 + 255) / 256, 256>>>(hlinh, cur, bs + (l - 1) * DD,
                                              lng + l * DD, lnb + l * DD, nxt, 1,
                                              (l < 3) ? 1 : 0);
        cur = nxt;
    }

    // graph mean pooling
    k_pool<<<(NN + 127) / 128, 128>>>(out, batch, gout);
    k_final<<<GG, 128>>>(gout, batch);
}